// round 3
// baseline (speedup 1.0000x reference)
#include <cuda_runtime.h>

#define Hh 51
#define Rr 204      // 4*H gate rows
#define RP 224      // rows padded: 32 slots * 7 rows
#define RPT 7       // rows per thread (slot)
#define NBT 4       // batches per thread
#define HP 52       // layer-1 K (padded hidden), row stride of whh1
#define IN2 104     // layer-2 K ([h1;h2])
#define HS 108      // per-lane h row stride (16B-aligned)
#define Lt 999
#define NB 16       // batch per CTA
#define NCTA 128
#define THREADS 128
#define XCH 64      // time chunk for x/out staging
#define XCHP 65

// shared memory layout (floats)
#define OFF_WHH1 0
#define OFF_W2   (OFF_WHH1 + RP*HP)          // 11648
#define OFF_WIH1 (OFF_W2   + RP*IN2)         // +23296
#define OFF_B1   (OFF_WIH1 + RP)
#define OFF_B2   (OFF_B1   + RP)
#define OFF_WLIN (OFF_B2   + RP)             // 52 entries, [51] = b_lin
#define OFF_HROW (OFF_WLIN + HP)             // NB*HS: per-lane [h1(52) | h2(52+pad)]
#define OFF_C1   (OFF_HROW + NB*HS)
#define OFF_C2   (OFF_C1   + HP*NB)
#define OFF_G    (OFF_C2   + HP*NB)          // RP*NB activated gates
#define OFF_XCH  (OFF_G    + RP*NB)
#define OFF_OCH  (OFF_XCH  + NB*XCHP)
#define OFF_OP   (OFF_OCH  + NB*XCHP)        // 128 partials
#define SMEM_FLOATS (OFF_OP + THREADS)

typedef unsigned long long ull;

__device__ __forceinline__ ull pack2(float lo, float hi) {
    ull d; asm("mov.b64 %0, {%1, %2};" : "=l"(d) : "f"(lo), "f"(hi)); return d;
}
__device__ __forceinline__ void unpack2(ull v, float& lo, float& hi) {
    asm("mov.b64 {%0, %1}, %2;" : "=f"(lo), "=f"(hi) : "l"(v));
}
__device__ __forceinline__ void fma2(ull& d, ull a, ull b) {
    asm("fma.rn.f32x2 %0, %1, %2, %0;" : "+l"(d) : "l"(a), "l"(b));
}
__device__ __forceinline__ float sigf(float x) {
    return 1.0f / (1.0f + __expf(-x));
}
__device__ __forceinline__ float ftanh(float x) {
    return 1.0f - 2.0f / (__expf(2.0f * x) + 1.0f);
}

__global__ void __launch_bounds__(THREADS, 1)
lstm_kernel(const float* __restrict__ x,
            const float* __restrict__ gWih1, const float* __restrict__ gWhh1,
            const float* __restrict__ gbih1, const float* __restrict__ gbhh1,
            const float* __restrict__ gWih2, const float* __restrict__ gWhh2,
            const float* __restrict__ gbih2, const float* __restrict__ gbhh2,
            const float* __restrict__ gWlin, const float* __restrict__ gblin,
            float* __restrict__ out)
{
    extern __shared__ float sm[];
    float* whh1 = sm + OFF_WHH1;
    float* w2   = sm + OFF_W2;
    float* wih1 = sm + OFF_WIH1;
    float* b1   = sm + OFF_B1;
    float* b2   = sm + OFF_B2;
    float* wlin = sm + OFF_WLIN;
    float* hrow = sm + OFF_HROW;
    float* c1s  = sm + OFF_C1;
    float* c2s  = sm + OFF_C2;
    float* gsm  = sm + OFF_G;
    float* xch  = sm + OFF_XCH;
    float* och  = sm + OFF_OCH;
    float* opart= sm + OFF_OP;

    const int tid = threadIdx.x;
    const int g   = tid & 3;          // batch group: batches 4g..4g+3
    const int s   = tid >> 2;         // row slot 0..31
    const int r0  = s * RPT;
    const int b0  = blockIdx.x * NB;

    // ---- stage weights into smem (once) ----
    for (int i = tid; i < RP*HP; i += THREADS) {
        int r = i / HP, j = i - r*HP;
        whh1[i] = (r < Rr && j < Hh) ? gWhh1[r*Hh + j] : 0.f;
    }
    for (int i = tid; i < RP*IN2; i += THREADS) {
        int r = i / IN2, j = i - r*IN2;
        float v = 0.f;
        if (r < Rr) {
            if (j < Hh)                    v = gWih2[r*Hh + j];
            else if (j >= HP && j < HP+Hh) v = gWhh2[r*Hh + (j - HP)];
        }
        w2[i] = v;
    }
    for (int i = tid; i < RP; i += THREADS) {
        wih1[i] = (i < Rr) ? gWih1[i] : 0.f;
        b1[i]   = (i < Rr) ? (gbih1[i] + gbhh1[i]) : 0.f;
        b2[i]   = (i < Rr) ? (gbih2[i] + gbhh2[i]) : 0.f;
    }
    if (tid < HP) wlin[tid] = (tid < Hh) ? gWlin[tid] : ((tid == Hh) ? gblin[0] : 0.f);
    for (int i = tid; i < NB*HS; i += THREADS) hrow[i] = 0.f;
    for (int i = tid; i < HP*NB; i += THREADS) { c1s[i] = 0.f; c2s[i] = 0.f; }
    __syncthreads();

    int t0 = 0;
    for (int t = 0; t < Lt; ++t) {
        // ---- chunk boundary: stage x (coalesced) ----
        if ((t & (XCH-1)) == 0) {
            t0 = t;
            int w = Lt - t0; if (w > XCH) w = XCH;
            for (int i = tid; i < NB*XCH; i += THREADS) {
                int row = i >> 6, col = i & 63;
                xch[row*XCHP + col] = (col < w) ? x[(b0+row)*Lt + t0 + col] : 0.f;
            }
            __syncthreads();
        }
        const int tloc = t - t0;

        // ---- Stage A: layer-1 gates for 7 rows x 4 batches ----
        {
            ull acc[RPT][NBT];
            #pragma unroll
            for (int i = 0; i < NBT; i++) {
                const float xv = xch[(4*g + i)*XCHP + tloc];
                #pragma unroll
                for (int rr = 0; rr < RPT; rr++)
                    acc[rr][i] = pack2(fmaf(wih1[r0+rr], xv, b1[r0+rr]), 0.f);
            }
            #pragma unroll
            for (int jg = 0; jg < 13; jg++) {
                const int j = jg * 4;
                ull ha[NBT], hb[NBT];
                #pragma unroll
                for (int i = 0; i < NBT; i++) {
                    const ulonglong2 hv = *(const ulonglong2*)(hrow + (4*g+i)*HS + j);
                    ha[i] = hv.x; hb[i] = hv.y;
                }
                #pragma unroll
                for (int rr = 0; rr < RPT; rr++) {
                    const ulonglong2 wv = *(const ulonglong2*)(whh1 + (r0+rr)*HP + j);
                    #pragma unroll
                    for (int i = 0; i < NBT; i++) {
                        fma2(acc[rr][i], wv.x, ha[i]);
                        fma2(acc[rr][i], wv.y, hb[i]);
                    }
                }
            }
            #pragma unroll
            for (int rr = 0; rr < RPT; rr++) {
                const int r = r0 + rr;
                #pragma unroll
                for (int i = 0; i < NBT; i++) {
                    float lo, hi; unpack2(acc[rr][i], lo, hi);
                    float v = lo + hi;
                    v = (r >= 102 && r < 153) ? ftanh(v) : sigf(v);
                    gsm[r*NB + 4*g + i] = v;
                }
            }
        }
        __syncthreads();

        // ---- Stage B: layer-1 cell/hidden update (816 items) ----
        for (int it = tid; it < Hh*NB; it += THREADS) {
            const int u = it >> 4, lane = it & 15;
            const float ai = gsm[u*NB + lane];
            const float af = gsm[(51+u)*NB + lane];
            const float ag = gsm[(102+u)*NB + lane];
            const float ao = gsm[(153+u)*NB + lane];
            const float c  = c1s[u*NB + lane];
            const float cn = fmaf(af, c, ai*ag);
            c1s[u*NB + lane] = cn;
            hrow[lane*HS + u] = ao * ftanh(cn);
        }
        __syncthreads();

        // ---- Stage C: layer-2 gates ([Wih2|Whh2] @ [h1;h2]) ----
        {
            ull acc[RPT][NBT];
            #pragma unroll
            for (int rr = 0; rr < RPT; rr++) {
                const ull binit = pack2(b2[r0+rr], 0.f);
                #pragma unroll
                for (int i = 0; i < NBT; i++) acc[rr][i] = binit;
            }
            #pragma unroll
            for (int jg = 0; jg < 26; jg++) {
                const int j = jg * 4;
                ull ha[NBT], hb[NBT];
                #pragma unroll
                for (int i = 0; i < NBT; i++) {
                    const ulonglong2 hv = *(const ulonglong2*)(hrow + (4*g+i)*HS + j);
                    ha[i] = hv.x; hb[i] = hv.y;
                }
                #pragma unroll
                for (int rr = 0; rr < RPT; rr++) {
                    const ulonglong2 wv = *(const ulonglong2*)(w2 + (r0+rr)*IN2 + j);
                    #pragma unroll
                    for (int i = 0; i < NBT; i++) {
                        fma2(acc[rr][i], wv.x, ha[i]);
                        fma2(acc[rr][i], wv.y, hb[i]);
                    }
                }
            }
            #pragma unroll
            for (int rr = 0; rr < RPT; rr++) {
                const int r = r0 + rr;
                #pragma unroll
                for (int i = 0; i < NBT; i++) {
                    float lo, hi; unpack2(acc[rr][i], lo, hi);
                    float v = lo + hi;
                    v = (r >= 102 && r < 153) ? ftanh(v) : sigf(v);
                    gsm[r*NB + 4*g + i] = v;
                }
            }
        }
        __syncthreads();

        // ---- Stage D: layer-2 update + output partials ----
        {
            float op = 0.f;
            for (int it = tid; it < Hh*NB; it += THREADS) {
                const int u = it >> 4, lane = it & 15;
                const float ai = gsm[u*NB + lane];
                const float af = gsm[(51+u)*NB + lane];
                const float ag = gsm[(102+u)*NB + lane];
                const float ao = gsm[(153+u)*NB + lane];
                const float c  = c2s[u*NB + lane];
                const float cn = fmaf(af, c, ai*ag);
                const float hn = ao * ftanh(cn);
                c2s[u*NB + lane] = cn;
                hrow[lane*HS + HP + u] = hn;
                op = fmaf(hn, wlin[u], op);
            }
            opart[tid] = op;   // all items of this thread share lane = tid&15
        }
        __syncthreads();

        // ---- Stage E: reduce output per batch, buffer in smem ----
        if (tid < NB) {
            float sacc = opart[tid];
            #pragma unroll
            for (int q = 1; q < THREADS/NB; q++) sacc += opart[q*NB + tid];
            och[tid*XCHP + tloc] = sacc + wlin[Hh];   // + b_lin
        }

        // ---- flush output chunk (coalesced) ----
        if (tloc == XCH-1 || t == Lt-1) {
            __syncthreads();
            const int w = tloc + 1;
            for (int i = tid; i < NB*w; i += THREADS) {
                const int row = i / w, col = i - row*w;
                out[(b0+row)*Lt + t0 + col] = och[row*XCHP + col];
            }
        }
    }
}

extern "C" void kernel_launch(void* const* d_in, const int* in_sizes, int n_in,
                              void* d_out, int out_size)
{
    const float* x     = (const float*)d_in[0];
    const float* wih1  = (const float*)d_in[1];
    const float* whh1  = (const float*)d_in[2];
    const float* bih1  = (const float*)d_in[3];
    const float* bhh1  = (const float*)d_in[4];
    const float* wih2  = (const float*)d_in[5];
    const float* whh2  = (const float*)d_in[6];
    const float* bih2  = (const float*)d_in[7];
    const float* bhh2  = (const float*)d_in[8];
    const float* wlin  = (const float*)d_in[9];
    const float* blin  = (const float*)d_in[10];
    float* out = (float*)d_out;

    const size_t smem = (size_t)SMEM_FLOATS * sizeof(float);
    cudaFuncSetAttribute(lstm_kernel, cudaFuncAttributeMaxDynamicSharedMemorySize, (int)smem);
    lstm_kernel<<<NCTA, THREADS, smem>>>(x, wih1, whh1, bih1, bhh1,
                                         wih2, whh2, bih2, bhh2,
                                         wlin, blin, out);
}

// round 4
// speedup vs baseline: 1.6726x; 1.6726x over previous
#include <cuda_runtime.h>

#define Hh 51
#define Rr 204      // 4*H gate rows
#define RP 224      // rows padded: 32 slots * 7 rows
#define RPT 7       // rows per thread (slot)
#define NBT 2       // batches per thread (g and g+8)
#define HP 52       // layer-1 K (padded hidden), row stride of whh1
#define IN2 104     // layer-2 K ([h1;h2])
#define HS 132      // per-lane h row stride: 132*4 % 128 == 16 -> conflict-free 16B loads
#define Lt 999
#define NB 16       // batch per CTA
#define NCTA 128
#define THREADS 256
#define XCH 64      // time chunk for x/out staging
#define XCHP 65

// shared memory layout (floats)
#define OFF_WHH1 0
#define OFF_W2   (OFF_WHH1 + RP*HP)
#define OFF_WIH1 (OFF_W2   + RP*IN2)
#define OFF_B1   (OFF_WIH1 + RP)
#define OFF_B2   (OFF_B1   + RP)
#define OFF_WLIN (OFF_B2   + RP)             // 52 entries, [51] = b_lin
#define OFF_HROW (OFF_WLIN + HP)             // NB*HS: per-batch [h1(52) | h2(52)] rows
#define OFF_C1   (OFF_HROW + NB*HS)
#define OFF_C2   (OFF_C1   + HP*NB)
#define OFF_G    (OFF_C2   + HP*NB)          // RP*NB activated gates
#define OFF_XCH  (OFF_G    + RP*NB)
#define OFF_OCH  (OFF_XCH  + NB*XCHP)
#define OFF_OP   (OFF_OCH  + NB*XCHP)        // 256 partials
#define SMEM_FLOATS (OFF_OP + THREADS)

typedef unsigned long long ull;

__device__ __forceinline__ ull pack2(float lo, float hi) {
    ull d; asm("mov.b64 %0, {%1, %2};" : "=l"(d) : "f"(lo), "f"(hi)); return d;
}
__device__ __forceinline__ void unpack2(ull v, float& lo, float& hi) {
    asm("mov.b64 {%0, %1}, %2;" : "=f"(lo), "=f"(hi) : "l"(v));
}
__device__ __forceinline__ void fma2(ull& d, ull a, ull b) {
    asm("fma.rn.f32x2 %0, %1, %2, %0;" : "+l"(d) : "l"(a), "l"(b));
}
__device__ __forceinline__ float sigf(float x) {
    return 1.0f / (1.0f + __expf(-x));
}
__device__ __forceinline__ float ftanh(float x) {
    return 1.0f - 2.0f / (__expf(2.0f * x) + 1.0f);
}

__global__ void __launch_bounds__(THREADS, 1)
lstm_kernel(const float* __restrict__ x,
            const float* __restrict__ gWih1, const float* __restrict__ gWhh1,
            const float* __restrict__ gbih1, const float* __restrict__ gbhh1,
            const float* __restrict__ gWih2, const float* __restrict__ gWhh2,
            const float* __restrict__ gbih2, const float* __restrict__ gbhh2,
            const float* __restrict__ gWlin, const float* __restrict__ gblin,
            float* __restrict__ out)
{
    extern __shared__ float sm[];
    float* whh1 = sm + OFF_WHH1;
    float* w2   = sm + OFF_W2;
    float* wih1 = sm + OFF_WIH1;
    float* b1   = sm + OFF_B1;
    float* b2   = sm + OFF_B2;
    float* wlin = sm + OFF_WLIN;
    float* hrow = sm + OFF_HROW;
    float* c1s  = sm + OFF_C1;
    float* c2s  = sm + OFF_C2;
    float* gsm  = sm + OFF_G;
    float* xch  = sm + OFF_XCH;
    float* och  = sm + OFF_OCH;
    float* opart= sm + OFF_OP;

    const int tid = threadIdx.x;
    const int g   = tid & 7;          // batch group: handles batches g and g+8
    const int s   = tid >> 3;         // row slot 0..31
    const int r0  = s * RPT;
    const int b0  = blockIdx.x * NB;

    // ---- stage weights into smem (once) ----
    for (int i = tid; i < RP*HP; i += THREADS) {
        int r = i / HP, j = i - r*HP;
        whh1[i] = (r < Rr && j < Hh) ? gWhh1[r*Hh + j] : 0.f;
    }
    for (int i = tid; i < RP*IN2; i += THREADS) {
        int r = i / IN2, j = i - r*IN2;
        float v = 0.f;
        if (r < Rr) {
            if (j < Hh)                    v = gWih2[r*Hh + j];
            else if (j >= HP && j < HP+Hh) v = gWhh2[r*Hh + (j - HP)];
        }
        w2[i] = v;
    }
    for (int i = tid; i < RP; i += THREADS) {
        wih1[i] = (i < Rr) ? gWih1[i] : 0.f;
        b1[i]   = (i < Rr) ? (gbih1[i] + gbhh1[i]) : 0.f;
        b2[i]   = (i < Rr) ? (gbih2[i] + gbhh2[i]) : 0.f;
    }
    if (tid < HP) wlin[tid] = (tid < Hh) ? gWlin[tid] : ((tid == Hh) ? gblin[0] : 0.f);
    for (int i = tid; i < NB*HS; i += THREADS) hrow[i] = 0.f;
    for (int i = tid; i < HP*NB; i += THREADS) { c1s[i] = 0.f; c2s[i] = 0.f; }
    __syncthreads();

    const float* hb0 = hrow + g * HS;          // batch g
    const float* hb1 = hrow + (g + 8) * HS;    // batch g+8

    int t0 = 0;
    for (int t = 0; t < Lt; ++t) {
        // ---- chunk boundary: stage x (coalesced) ----
        if ((t & (XCH-1)) == 0) {
            t0 = t;
            int w = Lt - t0; if (w > XCH) w = XCH;
            for (int i = tid; i < NB*XCH; i += THREADS) {
                int row = i >> 6, col = i & 63;
                xch[row*XCHP + col] = (col < w) ? x[(b0+row)*Lt + t0 + col] : 0.f;
            }
            __syncthreads();
        }
        const int tloc = t - t0;

        // ---- Stage A: layer-1 gates: 7 rows x 2 batches ----
        {
            ull acc0[RPT], acc1[RPT];
            const float xv0 = xch[g*XCHP + tloc];
            const float xv1 = xch[(g+8)*XCHP + tloc];
            #pragma unroll
            for (int rr = 0; rr < RPT; rr++) {
                const float wi = wih1[r0+rr], bb = b1[r0+rr];
                acc0[rr] = pack2(fmaf(wi, xv0, bb), 0.f);
                acc1[rr] = pack2(fmaf(wi, xv1, bb), 0.f);
            }
            #pragma unroll
            for (int jg = 0; jg < 13; jg++) {
                const int j = jg * 4;
                const ulonglong2 h0 = *(const ulonglong2*)(hb0 + j);
                const ulonglong2 h1 = *(const ulonglong2*)(hb1 + j);
                #pragma unroll
                for (int rr = 0; rr < RPT; rr++) {
                    const ulonglong2 wv = *(const ulonglong2*)(whh1 + (r0+rr)*HP + j);
                    fma2(acc0[rr], wv.x, h0.x);
                    fma2(acc0[rr], wv.y, h0.y);
                    fma2(acc1[rr], wv.x, h1.x);
                    fma2(acc1[rr], wv.y, h1.y);
                }
            }
            #pragma unroll
            for (int rr = 0; rr < RPT; rr++) {
                const int r = r0 + rr;
                float lo, hi, v0, v1;
                unpack2(acc0[rr], lo, hi); v0 = lo + hi;
                unpack2(acc1[rr], lo, hi); v1 = lo + hi;
                if (r >= 102 && r < 153) { v0 = ftanh(v0); v1 = ftanh(v1); }
                else                     { v0 = sigf(v0);  v1 = sigf(v1);  }
                gsm[r*NB + g]     = v0;
                gsm[r*NB + 8 + g] = v1;
            }
        }
        __syncthreads();

        // ---- Stage B: layer-1 cell/hidden update (816 items, 256 threads) ----
        for (int it = tid; it < Hh*NB; it += THREADS) {
            const int u = it >> 4, lane = it & 15;
            const float ai = gsm[u*NB + lane];
            const float af = gsm[(51+u)*NB + lane];
            const float ag = gsm[(102+u)*NB + lane];
            const float ao = gsm[(153+u)*NB + lane];
            const float c  = c1s[u*NB + lane];
            const float cn = fmaf(af, c, ai*ag);
            c1s[u*NB + lane] = cn;
            hrow[lane*HS + u] = ao * ftanh(cn);
        }
        __syncthreads();

        // ---- Stage C: layer-2 gates ([Wih2|Whh2] @ [h1;h2]) ----
        {
            ull acc0[RPT], acc1[RPT];
            #pragma unroll
            for (int rr = 0; rr < RPT; rr++) {
                const ull binit = pack2(b2[r0+rr], 0.f);
                acc0[rr] = binit; acc1[rr] = binit;
            }
            #pragma unroll
            for (int jg = 0; jg < 26; jg++) {
                const int j = jg * 4;
                const ulonglong2 h0 = *(const ulonglong2*)(hb0 + j);
                const ulonglong2 h1 = *(const ulonglong2*)(hb1 + j);
                #pragma unroll
                for (int rr = 0; rr < RPT; rr++) {
                    const ulonglong2 wv = *(const ulonglong2*)(w2 + (r0+rr)*IN2 + j);
                    fma2(acc0[rr], wv.x, h0.x);
                    fma2(acc0[rr], wv.y, h0.y);
                    fma2(acc1[rr], wv.x, h1.x);
                    fma2(acc1[rr], wv.y, h1.y);
                }
            }
            #pragma unroll
            for (int rr = 0; rr < RPT; rr++) {
                const int r = r0 + rr;
                float lo, hi, v0, v1;
                unpack2(acc0[rr], lo, hi); v0 = lo + hi;
                unpack2(acc1[rr], lo, hi); v1 = lo + hi;
                if (r >= 102 && r < 153) { v0 = ftanh(v0); v1 = ftanh(v1); }
                else                     { v0 = sigf(v0);  v1 = sigf(v1);  }
                gsm[r*NB + g]     = v0;
                gsm[r*NB + 8 + g] = v1;
            }
        }
        __syncthreads();

        // ---- Stage D: layer-2 update + output partials ----
        {
            float op = 0.f;
            for (int it = tid; it < Hh*NB; it += THREADS) {
                const int u = it >> 4, lane = it & 15;
                const float ai = gsm[u*NB + lane];
                const float af = gsm[(51+u)*NB + lane];
                const float ag = gsm[(102+u)*NB + lane];
                const float ao = gsm[(153+u)*NB + lane];
                const float c  = c2s[u*NB + lane];
                const float cn = fmaf(af, c, ai*ag);
                const float hn = ao * ftanh(cn);
                c2s[u*NB + lane] = cn;
                hrow[lane*HS + HP + u] = hn;
                op = fmaf(hn, wlin[u], op);
            }
            opart[tid] = op;   // lane = tid&15 is invariant across this thread's items
        }
        __syncthreads();

        // ---- Stage E: reduce output per batch, buffer in smem ----
        if (tid < NB) {
            float sacc = opart[tid];
            #pragma unroll
            for (int q = 1; q < THREADS/NB; q++) sacc += opart[q*NB + tid];
            och[tid*XCHP + tloc] = sacc + wlin[Hh];   // + b_lin
        }

        // ---- flush output chunk (coalesced) ----
        if (tloc == XCH-1 || t == Lt-1) {
            __syncthreads();
            const int w = tloc + 1;
            for (int i = tid; i < NB*w; i += THREADS) {
                const int row = i / w, col = i - row*w;
                out[(b0+row)*Lt + t0 + col] = och[row*XCHP + col];
            }
        }
    }
}

extern "C" void kernel_launch(void* const* d_in, const int* in_sizes, int n_in,
                              void* d_out, int out_size)
{
    const float* x     = (const float*)d_in[0];
    const float* wih1  = (const float*)d_in[1];
    const float* whh1  = (const float*)d_in[2];
    const float* bih1  = (const float*)d_in[3];
    const float* bhh1  = (const float*)d_in[4];
    const float* wih2  = (const float*)d_in[5];
    const float* whh2  = (const float*)d_in[6];
    const float* bih2  = (const float*)d_in[7];
    const float* bhh2  = (const float*)d_in[8];
    const float* wlin  = (const float*)d_in[9];
    const float* blin  = (const float*)d_in[10];
    float* out = (float*)d_out;

    const size_t smem = (size_t)SMEM_FLOATS * sizeof(float);
    cudaFuncSetAttribute(lstm_kernel, cudaFuncAttributeMaxDynamicSharedMemorySize, (int)smem);
    lstm_kernel<<<NCTA, THREADS, smem>>>(x, wih1, whh1, bih1, bhh1,
                                         wih2, whh2, bih2, bhh2,
                                         wlin, blin, out);
}

// round 5
// speedup vs baseline: 3.4923x; 2.0879x over previous
#include <cuda_runtime.h>
#include <cstdint>

#define Hh 51
#define Lt 999
#define NB 16
#define NCTA 128
#define THREADS 256
#define WARPS 8
#define NTW 4          // n8-tiles per warp (32 tiles = 256 padded gate rows)
#define NC1 7          // K-chunks layer1 (K=56: h1[51] + x + 1 + pad)
#define NC2 14         // K-chunks layer2 (K=112: [h1|x|1|pad ; h2|pad])
#define XCHP 65

// shared memory float offsets
#define OFF_B1PK 0
#define SZ_B1PK (32*NC1*64)              // 14336
#define OFF_B2PK (OFF_B1PK + SZ_B1PK)
#define SZ_B2PK (32*NC2*64)              // 28672
#define OFF_HBUF (OFF_B2PK + SZ_B2PK)    // 4 regions (P0,P1,Q0,Q1) x 7 chunks x 128
#define SZ_HBUF (4*NC1*128)              // 3584
#define OFF_XCH  (OFF_HBUF + SZ_HBUF)
#define OFF_OCH  (OFF_XCH + NB*XCHP)
#define OFF_OP   (OFF_OCH + NB*XCHP)     // 8 warps x 16
#define OFF_BLIN (OFF_OP + WARPS*NB)
#define SMEM_FLOATS (OFF_BLIN + 4)

__device__ __forceinline__ uint32_t to_tf32(float x) {
    uint32_t u; asm("cvt.rna.tf32.f32 %0, %1;" : "=r"(u) : "f"(x)); return u;
}
__device__ __forceinline__ void mma8(float* d, uint4 a, uint2 b) {
    asm("mma.sync.aligned.m16n8k8.row.col.f32.tf32.tf32.f32 "
        "{%0,%1,%2,%3}, {%4,%5,%6,%7}, {%8,%9}, {%0,%1,%2,%3};"
        : "+f"(d[0]), "+f"(d[1]), "+f"(d[2]), "+f"(d[3])
        : "r"(a.x), "r"(a.y), "r"(a.z), "r"(a.w), "r"(b.x), "r"(b.y));
}
__device__ __forceinline__ float sigf(float x) {
    return 1.0f / (1.0f + __expf(-x));
}
__device__ __forceinline__ float ftanh(float x) {
    return 1.0f - 2.0f / (__expf(2.0f * x) + 1.0f);
}
// hbuf slot for value (batch b, unit u) in fragment-permuted layout
__device__ __forceinline__ int hidx(int region, int b, int u) {
    const int colin = u & 7, ch = u >> 3;
    const int tl = ((b & 7) << 2) + (colin & 3);
    const int reg = ((colin >= 4) ? 2 : 0) + ((b >= 8) ? 1 : 0);
    return region*(NC1*128) + ch*128 + tl*4 + reg;
}

__global__ void __launch_bounds__(THREADS, 1)
lstm_kernel(const float* __restrict__ x,
            const float* __restrict__ gWih1, const float* __restrict__ gWhh1,
            const float* __restrict__ gbih1, const float* __restrict__ gbhh1,
            const float* __restrict__ gWih2, const float* __restrict__ gWhh2,
            const float* __restrict__ gbih2, const float* __restrict__ gbhh2,
            const float* __restrict__ gWlin, const float* __restrict__ gblin,
            float* __restrict__ out)
{
    extern __shared__ float sm[];
    float* b1pk = sm + OFF_B1PK;
    float* b2pk = sm + OFF_B2PK;
    float* hbuf = sm + OFF_HBUF;
    uint32_t* hbu = (uint32_t*)hbuf;
    float* xch  = sm + OFF_XCH;
    float* och  = sm + OFF_OCH;
    float* opart= sm + OFF_OP;

    const int tid  = threadIdx.x;
    const int wid  = tid >> 5;
    const int lane = tid & 31;
    const int gid  = lane >> 2, tq = lane & 3;
    const int bmy  = gid + ((tq & 1) << 3);   // this lane's batch
    const int uh   = tq >> 1;                 // unit half within tile
    const int b0   = blockIdx.x * NB;

    // ---- pack layer-1 weights into per-lane fragment order (tf32) ----
    for (int idx = tid; idx < SZ_B1PK; idx += THREADS) {
        const int r   = idx & 1;
        const int ln  = (idx >> 1) & 31;
        const int c   = (idx >> 6) % NC1;
        const int tau = idx / (NC1 * 64);
        const int n = tau*8 + (ln >> 2);      // padded interleaved row 0..255
        const int u = n >> 2, ty = n & 3;     // unit, gate type (i,f,g,o)
        const int k = c*8 + (ln & 3) + 4*r;
        float v = 0.f;
        if (u < Hh) {
            const int R = ty*Hh + u;
            if (k < Hh)          v = gWhh1[R*Hh + k];
            else if (k == Hh)    v = gWih1[R];            // x slot (unit 51)
            else if (k == Hh+1)  v = gbih1[R] + gbhh1[R]; // const-1 slot (unit 52)
        }
        b1pk[idx] = __uint_as_float(to_tf32(v));
    }
    // ---- pack layer-2 weights ----
    for (int idx = tid; idx < SZ_B2PK; idx += THREADS) {
        const int r   = idx & 1;
        const int ln  = (idx >> 1) & 31;
        const int c   = (idx >> 6) % NC2;
        const int tau = idx / (NC2 * 64);
        const int n = tau*8 + (ln >> 2);
        const int u = n >> 2, ty = n & 3;
        const int k = c*8 + (ln & 3) + 4*r;
        float v = 0.f;
        if (u < Hh) {
            const int R = ty*Hh + u;
            if (k < Hh)          v = gWih2[R*Hh + k];       // h1 side
            else if (k == Hh+1)  v = gbih2[R] + gbhh2[R];   // const-1 slot
            else if (k >= 56) { const int kq = k - 56; if (kq < Hh) v = gWhh2[R*Hh + kq]; }
        }
        b2pk[idx] = __uint_as_float(to_tf32(v));
    }
    for (int i = tid; i < SZ_HBUF; i += THREADS) hbuf[i] = 0.f;
    if (tid == 0) sm[OFF_BLIN] = gblin[0];
    __syncthreads();
    // const-1 (both P regions) + x_0 (P0)
    if (tid < NB) {
        const uint32_t one = to_tf32(1.0f);
        hbu[hidx(0, tid, 52)] = one;
        hbu[hidx(1, tid, 52)] = one;
        hbu[hidx(0, tid, 51)] = to_tf32(x[(b0 + tid)*Lt + 0]);
    }
    // per-lane W_lin for this lane's L2 units
    float wl[NTW];
    #pragma unroll
    for (int j = 0; j < NTW; j++) {
        const int u = 2*(wid + 8*j) + uh;
        wl[j] = (u < Hh) ? gWlin[u] : 0.f;
    }
    float cst1[NTW] = {0.f,0.f,0.f,0.f}, cst2[NTW] = {0.f,0.f,0.f,0.f};
    __syncthreads();

    int t0 = 0;
    for (int t = 0; t < Lt; ++t) {
        // ---- chunk boundary: stage x (coalesced) ----
        if ((t & 63) == 0) {
            t0 = t;
            int wd = Lt - t0; if (wd > 64) wd = 64;
            for (int i = tid; i < NB*64; i += THREADS) {
                const int row = i >> 6, col = i & 63;
                xch[row*XCHP + col] = (col < wd) ? x[(b0+row)*Lt + t0 + col] : 0.f;
            }
            __syncthreads();
            if (t0 > 0 && tid < NB)
                hbu[hidx(t0 & 1, tid, 51)] = to_tf32(xch[tid*XCHP + 0]);
            __syncthreads();
        }
        const int tloc = t - t0;
        const int pr = t & 1, pw = 1 - pr;       // P (h1) regions: read/write
        const int qr = 2 + pr, qw = 2 + pw;      // Q (h2) regions

        // ================= Layer 1 =================
        float acc[NTW][4];
        #pragma unroll
        for (int j = 0; j < NTW; j++) { acc[j][0]=acc[j][1]=acc[j][2]=acc[j][3]=0.f; }
        #pragma unroll
        for (int c = 0; c < NC1; c++) {
            const uint4 av = *(const uint4*)&hbuf[pr*(NC1*128) + c*128 + lane*4];
            #pragma unroll
            for (int j = 0; j < NTW; j++) {
                const int tau = wid + 8*j;
                const uint2 bv = *(const uint2*)&b1pk[((tau*NC1 + c)*32 + lane)*2];
                mma8(acc[j], av, bv);
            }
        }
        #pragma unroll
        for (int j = 0; j < NTW; j++) {
            const int u = 2*(wid + 8*j) + uh;
            const float sA = (tq & 1) ? acc[j][0] : acc[j][2];
            const float sB = (tq & 1) ? acc[j][1] : acc[j][3];
            const float rA = __shfl_xor_sync(0xffffffffu, sA, 1);
            const float rB = __shfl_xor_sync(0xffffffffu, sB, 1);
            float gi, gf, gg, go;
            if (tq & 1) { gi = rA; gf = rB; gg = acc[j][2]; go = acc[j][3]; }
            else        { gi = acc[j][0]; gf = acc[j][1]; gg = rA; go = rB; }
            const float cn = fmaf(sigf(gf), cst1[j], sigf(gi)*ftanh(gg));
            cst1[j] = cn;
            const float hn = sigf(go) * ftanh(cn);
            if (u < Hh) hbu[hidx(pw, bmy, u)] = to_tf32(hn);
        }
        if (tid < NB && tloc < 63 && t+1 < Lt)
            hbu[hidx(pw, tid, 51)] = to_tf32(xch[tid*XCHP + tloc + 1]);
        __syncthreads();   // B2: new h1 (+x) visible

        // ================= Layer 2 =================
        #pragma unroll
        for (int j = 0; j < NTW; j++) { acc[j][0]=acc[j][1]=acc[j][2]=acc[j][3]=0.f; }
        #pragma unroll
        for (int c = 0; c < NC2; c++) {
            const int reg = (c < NC1) ? pw : qr;
            const int cc  = (c < NC1) ? c : c - NC1;
            const uint4 av = *(const uint4*)&hbuf[reg*(NC1*128) + cc*128 + lane*4];
            #pragma unroll
            for (int j = 0; j < NTW; j++) {
                const int tau = wid + 8*j;
                const uint2 bv = *(const uint2*)&b2pk[((tau*NC2 + c)*32 + lane)*2];
                mma8(acc[j], av, bv);
            }
        }
        float ypart = 0.f;
        #pragma unroll
        for (int j = 0; j < NTW; j++) {
            const int u = 2*(wid + 8*j) + uh;
            const float sA = (tq & 1) ? acc[j][0] : acc[j][2];
            const float sB = (tq & 1) ? acc[j][1] : acc[j][3];
            const float rA = __shfl_xor_sync(0xffffffffu, sA, 1);
            const float rB = __shfl_xor_sync(0xffffffffu, sB, 1);
            float gi, gf, gg, go;
            if (tq & 1) { gi = rA; gf = rB; gg = acc[j][2]; go = acc[j][3]; }
            else        { gi = acc[j][0]; gf = acc[j][1]; gg = rA; go = rB; }
            const float cn = fmaf(sigf(gf), cst2[j], sigf(gi)*ftanh(gg));
            cst2[j] = cn;
            const float hn = sigf(go) * ftanh(cn);
            if (u < Hh) hbu[hidx(qw, bmy, u)] = to_tf32(hn);
            ypart = fmaf(hn, wl[j], ypart);
        }
        const float ys = ypart + __shfl_xor_sync(0xffffffffu, ypart, 2);
        if (tq < 2) opart[wid*NB + ((tq & 1) << 3) + gid] = ys;
        __syncthreads();   // B3: h2 + opart visible

        if (tid < NB) {
            float s = sm[OFF_BLIN];
            #pragma unroll
            for (int w8 = 0; w8 < WARPS; w8++) s += opart[w8*NB + tid];
            och[tid*XCHP + tloc] = s;
        }

        // ---- flush output chunk (coalesced) ----
        if (tloc == 63 || t == Lt-1) {
            __syncthreads();
            const int wd = tloc + 1;
            for (int i = tid; i < NB*wd; i += THREADS) {
                const int row = i / wd, col = i - row*wd;
                out[(b0+row)*Lt + t0 + col] = och[row*XCHP + col];
            }
        }
    }
}

extern "C" void kernel_launch(void* const* d_in, const int* in_sizes, int n_in,
                              void* d_out, int out_size)
{
    const float* x     = (const float*)d_in[0];
    const float* wih1  = (const float*)d_in[1];
    const float* whh1  = (const float*)d_in[2];
    const float* bih1  = (const float*)d_in[3];
    const float* bhh1  = (const float*)d_in[4];
    const float* wih2  = (const float*)d_in[5];
    const float* whh2  = (const float*)d_in[6];
    const float* bih2  = (const float*)d_in[7];
    const float* bhh2  = (const float*)d_in[8];
    const float* wlin  = (const float*)d_in[9];
    const float* blin  = (const float*)d_in[10];
    float* out = (float*)d_out;

    const size_t smem = (size_t)SMEM_FLOATS * sizeof(float);
    cudaFuncSetAttribute(lstm_kernel, cudaFuncAttributeMaxDynamicSharedMemorySize, (int)smem);
    lstm_kernel<<<NCTA, THREADS, smem>>>(x, wih1, whh1, bih1, bhh1,
                                         wih2, whh2, bih2, bhh2,
                                         wlin, blin, out);
}

// round 6
// speedup vs baseline: 4.8924x; 1.4009x over previous
#include <cuda_runtime.h>
#include <cstdint>

#define Hh 51
#define Lt 999
#define NB 16
#define NCTA 128
#define THREADS 256
#define WARPS 8
#define NTW 4          // n8-tiles per warp (32 tiles = 256 padded gate rows)
#define NC1 7          // K-chunks layer1 (K=56: h1[51] + x + pad)
#define NC2 14         // K-chunks layer2 (K=112)
#define XCHP 65
#define RSTRIDE (2*NC1*128)   // per-region floats (hi+lo planes)

// shared memory float offsets
#define OFF_B1PK 0
#define SZ_B1PK (32*NC1*64)              // 14336
#define OFF_B2PK (OFF_B1PK + SZ_B1PK)
#define SZ_B2PK (32*NC2*64)              // 28672
#define OFF_HBUF (OFF_B2PK + SZ_B2PK)    // 4 regions x (hi,lo) x 7 chunks x 128
#define SZ_HBUF (4*RSTRIDE)              // 7168
#define OFF_XCH  (OFF_HBUF + SZ_HBUF)
#define OFF_OCH  (OFF_XCH + NB*XCHP)
#define OFF_OP   (OFF_OCH + NB*XCHP)     // 8 warps x 16
#define OFF_BLIN (OFF_OP + WARPS*NB)
#define SMEM_FLOATS (OFF_BLIN + 4)

__device__ __forceinline__ uint32_t to_tf32(float x) {
    uint32_t u; asm("cvt.rna.tf32.f32 %0, %1;" : "=r"(u) : "f"(x)); return u;
}
__device__ __forceinline__ void mma8(float* d, uint4 a, uint2 b) {
    asm("mma.sync.aligned.m16n8k8.row.col.f32.tf32.tf32.f32 "
        "{%0,%1,%2,%3}, {%4,%5,%6,%7}, {%8,%9}, {%0,%1,%2,%3};"
        : "+f"(d[0]), "+f"(d[1]), "+f"(d[2]), "+f"(d[3])
        : "r"(a.x), "r"(a.y), "r"(a.z), "r"(a.w), "r"(b.x), "r"(b.y));
}
__device__ __forceinline__ float frcp(float x) {
    float r; asm("rcp.approx.f32 %0, %1;" : "=f"(r) : "f"(x)); return r;
}
__device__ __forceinline__ float fex2(float x) {
    float r; asm("ex2.approx.f32 %0, %1;" : "=f"(r) : "f"(x)); return r;
}
__device__ __forceinline__ float sigf(float x) {
    return frcp(fex2(-1.4426950408889634f * x) + 1.0f);
}
__device__ __forceinline__ float ftanh(float x) {
    return fmaf(-2.0f, frcp(fex2(2.8853901817779268f * x) + 1.0f), 1.0f);
}
// hbuf slot for value (batch b, unit u), plane 0=hi 1=lo
__device__ __forceinline__ int hidx(int region, int plane, int b, int u) {
    const int colin = u & 7, ch = u >> 3;
    const int tl = ((b & 7) << 2) + (colin & 3);
    const int reg = ((colin >= 4) ? 2 : 0) + ((b >= 8) ? 1 : 0);
    return region*RSTRIDE + plane*(NC1*128) + ch*128 + tl*4 + reg;
}

__global__ void __launch_bounds__(THREADS, 1)
lstm_kernel(const float* __restrict__ x,
            const float* __restrict__ gWih1, const float* __restrict__ gWhh1,
            const float* __restrict__ gbih1, const float* __restrict__ gbhh1,
            const float* __restrict__ gWih2, const float* __restrict__ gWhh2,
            const float* __restrict__ gbih2, const float* __restrict__ gbhh2,
            const float* __restrict__ gWlin, const float* __restrict__ gblin,
            float* __restrict__ out)
{
    extern __shared__ float sm[];
    float* b1pk = sm + OFF_B1PK;
    float* b2pk = sm + OFF_B2PK;
    float* hbuf = sm + OFF_HBUF;
    uint32_t* hbu = (uint32_t*)hbuf;
    float* xch  = sm + OFF_XCH;
    float* och  = sm + OFF_OCH;
    float* opart= sm + OFF_OP;

    const int tid  = threadIdx.x;
    const int wid  = tid >> 5;
    const int lane = tid & 31;
    const int gid  = lane >> 2, tq = lane & 3;
    const int bmy  = gid + ((tq & 1) << 3);   // this lane's batch
    const int uh   = tq >> 1;                 // unit half within tile
    const int b0   = blockIdx.x * NB;

    // ---- pack layer-1 weights (tf32, fragment order); bias column ZERO ----
    for (int idx = tid; idx < SZ_B1PK; idx += THREADS) {
        const int r   = idx & 1;
        const int ln  = (idx >> 1) & 31;
        const int c   = (idx >> 6) % NC1;
        const int tau = idx / (NC1 * 64);
        const int n = tau*8 + (ln >> 2);
        const int u = n >> 2, ty = n & 3;
        const int k = c*8 + (ln & 3) + 4*r;
        float v = 0.f;
        if (u < Hh) {
            const int R = ty*Hh + u;
            if (k < Hh)       v = gWhh1[R*Hh + k];
            else if (k == Hh) v = gWih1[R];          // x slot (unit 51)
        }
        b1pk[idx] = __uint_as_float(to_tf32(v));
    }
    // ---- pack layer-2 weights; x and bias columns ZERO ----
    for (int idx = tid; idx < SZ_B2PK; idx += THREADS) {
        const int r   = idx & 1;
        const int ln  = (idx >> 1) & 31;
        const int c   = (idx >> 6) % NC2;
        const int tau = idx / (NC2 * 64);
        const int n = tau*8 + (ln >> 2);
        const int u = n >> 2, ty = n & 3;
        const int k = c*8 + (ln & 3) + 4*r;
        float v = 0.f;
        if (u < Hh) {
            const int R = ty*Hh + u;
            if (k < Hh) v = gWih2[R*Hh + k];
            else if (k >= 56) { const int kq = k - 56; if (kq < Hh) v = gWhh2[R*Hh + kq]; }
        }
        b2pk[idx] = __uint_as_float(to_tf32(v));
    }
    for (int i = tid; i < SZ_HBUF; i += THREADS) hbuf[i] = 0.f;
    if (tid == 0) sm[OFF_BLIN] = gblin[0];
    __syncthreads();
    // x_0 (region P0, both planes)
    if (tid < NB) {
        const float xv = x[(b0 + tid)*Lt + 0];
        const uint32_t hi = to_tf32(xv);
        hbu[hidx(0, 0, tid, 51)] = hi;
        hbu[hidx(0, 1, tid, 51)] = to_tf32(xv - __uint_as_float(hi));
    }
    // per-lane exact bias + W_lin
    float wl[NTW], bs1[NTW][4], bs2[NTW][4];
    #pragma unroll
    for (int j = 0; j < NTW; j++) {
        const int u = 2*(wid + 8*j) + uh;
        wl[j] = (u < Hh) ? gWlin[u] : 0.f;
        #pragma unroll
        for (int ty = 0; ty < 4; ty++) {
            const int R = ty*Hh + u;
            bs1[j][ty] = (u < Hh) ? (gbih1[R] + gbhh1[R]) : 0.f;
            bs2[j][ty] = (u < Hh) ? (gbih2[R] + gbhh2[R]) : 0.f;
        }
    }
    float cst1[NTW] = {0.f,0.f,0.f,0.f}, cst2[NTW] = {0.f,0.f,0.f,0.f};
    __syncthreads();

    int t0 = 0;
    for (int t = 0; t < Lt; ++t) {
        // ---- chunk boundary: stage x (coalesced) ----
        if ((t & 63) == 0) {
            t0 = t;
            int wd = Lt - t0; if (wd > 64) wd = 64;
            for (int i = tid; i < NB*64; i += THREADS) {
                const int row = i >> 6, col = i & 63;
                xch[row*XCHP + col] = (col < wd) ? x[(b0+row)*Lt + t0 + col] : 0.f;
            }
            __syncthreads();
            if (t0 > 0 && tid < NB) {
                const float xv = xch[tid*XCHP + 0];
                const uint32_t hi = to_tf32(xv);
                hbu[hidx(t0 & 1, 0, tid, 51)] = hi;
                hbu[hidx(t0 & 1, 1, tid, 51)] = to_tf32(xv - __uint_as_float(hi));
            }
            __syncthreads();
        }
        const int tloc = t - t0;
        const int pr = t & 1, pw = 1 - pr;       // P (h1) regions
        const int qr = 2 + pr, qw = 2 + pw;      // Q (h2) regions

        // ================= Layer 1 =================
        float acc[NTW][4];
        #pragma unroll
        for (int j = 0; j < NTW; j++) { acc[j][0]=acc[j][1]=acc[j][2]=acc[j][3]=0.f; }
        #pragma unroll
        for (int c = 0; c < NC1; c++) {
            const uint4 ah = *(const uint4*)&hbuf[pr*RSTRIDE + c*128 + lane*4];
            const uint4 al = *(const uint4*)&hbuf[pr*RSTRIDE + NC1*128 + c*128 + lane*4];
            #pragma unroll
            for (int j = 0; j < NTW; j++) {
                const int tau = wid + 8*j;
                const uint2 bv = *(const uint2*)&b1pk[((tau*NC1 + c)*32 + lane)*2];
                mma8(acc[j], ah, bv);
                mma8(acc[j], al, bv);
            }
        }
        #pragma unroll
        for (int j = 0; j < NTW; j++) {
            const int u = 2*(wid + 8*j) + uh;
            const float sA = (tq & 1) ? acc[j][0] : acc[j][2];
            const float sB = (tq & 1) ? acc[j][1] : acc[j][3];
            const float rA = __shfl_xor_sync(0xffffffffu, sA, 1);
            const float rB = __shfl_xor_sync(0xffffffffu, sB, 1);
            float gi, gf, gg, go;
            if (tq & 1) { gi = rA; gf = rB; gg = acc[j][2]; go = acc[j][3]; }
            else        { gi = acc[j][0]; gf = acc[j][1]; gg = rA; go = rB; }
            const float cn = fmaf(sigf(gf + bs1[j][1]), cst1[j],
                                  sigf(gi + bs1[j][0]) * ftanh(gg + bs1[j][2]));
            cst1[j] = cn;
            const float hn = sigf(go + bs1[j][3]) * ftanh(cn);
            if (u < Hh) {
                const uint32_t hi = to_tf32(hn);
                hbu[hidx(pw, 0, bmy, u)] = hi;
                hbu[hidx(pw, 1, bmy, u)] = to_tf32(hn - __uint_as_float(hi));
            }
        }
        if (tid < NB && tloc < 63 && t+1 < Lt) {
            const float xv = xch[tid*XCHP + tloc + 1];
            const uint32_t hi = to_tf32(xv);
            hbu[hidx(pw, 0, tid, 51)] = hi;
            hbu[hidx(pw, 1, tid, 51)] = to_tf32(xv - __uint_as_float(hi));
        }
        __syncthreads();   // new h1 (+x) visible

        // ================= Layer 2 =================
        #pragma unroll
        for (int j = 0; j < NTW; j++) { acc[j][0]=acc[j][1]=acc[j][2]=acc[j][3]=0.f; }
        #pragma unroll
        for (int c = 0; c < NC2; c++) {
            const int reg = (c < NC1) ? pw : qr;
            const int cc  = (c < NC1) ? c : c - NC1;
            const uint4 ah = *(const uint4*)&hbuf[reg*RSTRIDE + cc*128 + lane*4];
            const uint4 al = *(const uint4*)&hbuf[reg*RSTRIDE + NC1*128 + cc*128 + lane*4];
            #pragma unroll
            for (int j = 0; j < NTW; j++) {
                const int tau = wid + 8*j;
                const uint2 bv = *(const uint2*)&b2pk[((tau*NC2 + c)*32 + lane)*2];
                mma8(acc[j], ah, bv);
                mma8(acc[j], al, bv);
            }
        }
        float ypart = 0.f;
        #pragma unroll
        for (int j = 0; j < NTW; j++) {
            const int u = 2*(wid + 8*j) + uh;
            const float sA = (tq & 1) ? acc[j][0] : acc[j][2];
            const float sB = (tq & 1) ? acc[j][1] : acc[j][3];
            const float rA = __shfl_xor_sync(0xffffffffu, sA, 1);
            const float rB = __shfl_xor_sync(0xffffffffu, sB, 1);
            float gi, gf, gg, go;
            if (tq & 1) { gi = rA; gf = rB; gg = acc[j][2]; go = acc[j][3]; }
            else        { gi = acc[j][0]; gf = acc[j][1]; gg = rA; go = rB; }
            const float cn = fmaf(sigf(gf + bs2[j][1]), cst2[j],
                                  sigf(gi + bs2[j][0]) * ftanh(gg + bs2[j][2]));
            cst2[j] = cn;
            const float hn = sigf(go + bs2[j][3]) * ftanh(cn);
            if (u < Hh) {
                const uint32_t hi = to_tf32(hn);
                hbu[hidx(qw, 0, bmy, u)] = hi;
                hbu[hidx(qw, 1, bmy, u)] = to_tf32(hn - __uint_as_float(hi));
            }
            ypart = fmaf(hn, wl[j], ypart);
        }
        const float ys = ypart + __shfl_xor_sync(0xffffffffu, ypart, 2);
        if (tq < 2) opart[wid*NB + ((tq & 1) << 3) + gid] = ys;
        __syncthreads();   // h2 + opart visible

        if (tid < NB) {
            float s = sm[OFF_BLIN];
            #pragma unroll
            for (int w8 = 0; w8 < WARPS; w8++) s += opart[w8*NB + tid];
            och[tid*XCHP + tloc] = s;
        }

        // ---- flush output chunk (coalesced) ----
        if (tloc == 63 || t == Lt-1) {
            __syncthreads();
            const int wd = tloc + 1;
            for (int i = tid; i < NB*wd; i += THREADS) {
                const int row = i / wd, col = i - row*wd;
                out[(b0+row)*Lt + t0 + col] = och[row*XCHP + col];
            }
        }
    }
}

extern "C" void kernel_launch(void* const* d_in, const int* in_sizes, int n_in,
                              void* d_out, int out_size)
{
    const float* x     = (const float*)d_in[0];
    const float* wih1  = (const float*)d_in[1];
    const float* whh1  = (const float*)d_in[2];
    const float* bih1  = (const float*)d_in[3];
    const float* bhh1  = (const float*)d_in[4];
    const float* wih2  = (const float*)d_in[5];
    const float* whh2  = (const float*)d_in[6];
    const float* bih2  = (const float*)d_in[7];
    const float* bhh2  = (const float*)d_in[8];
    const float* wlin  = (const float*)d_in[9];
    const float* blin  = (const float*)d_in[10];
    float* out = (float*)d_out;

    const size_t smem = (size_t)SMEM_FLOATS * sizeof(float);
    cudaFuncSetAttribute(lstm_kernel, cudaFuncAttributeMaxDynamicSharedMemorySize, (int)smem);
    lstm_kernel<<<NCTA, THREADS, smem>>>(x, wih1, whh1, bih1, bhh1,
                                         wih2, whh2, bih2, bhh2,
                                         wlin, blin, out);
}